// round 6
// baseline (speedup 1.0000x reference)
#include <cuda_runtime.h>

// Problem constants
#define B_  4
#define T_  1024
#define D_  512
#define C_  8
#define H_  8
#define HD_ 64
#define BT_ (B_ * T_)      // 4096
#define D3_ (3 * D_)       // 1536

// Scratch (device globals: allocation-free, graph-capture safe)
__device__ float g_qkv[BT_ * D3_];    // [B*T, 3D]  Q|K|V
__device__ float g_attn[BT_ * D_];    // [B*T, D]   pre-out-proj attention output
__device__ int   g_assign[BT_];       // cluster id per token
__device__ int   g_idx[B_ * C_ * T_]; // compacted token indices per (b,c)
__device__ int   g_cnt[B_ * C_];      // cluster sizes per (b,c)

// ---------------------------------------------------------------------------
// Kernel 1: cluster scores + argmax.  One warp per token, Wc cached in smem.
// Strict '>' keeps the first max -> matches jnp.argmax tie behavior.
// ---------------------------------------------------------------------------
__global__ void assign_kernel(const float* __restrict__ X,
                              const float* __restrict__ Wc,
                              const float* __restrict__ bc)
{
    __shared__ float sWc[C_ * D_];
    __shared__ float sbc[C_];
    int tid = threadIdx.x; // 128
    for (int i = tid; i < C_ * D_; i += 128) sWc[i] = Wc[i];
    if (tid < C_) sbc[tid] = bc[tid];
    __syncthreads();

    int lane = tid & 31, w = tid >> 5;
    int token = blockIdx.x * 4 + w;
    const float* xr = X + (size_t)token * D_;

    float sc[C_];
#pragma unroll
    for (int c = 0; c < C_; c++) sc[c] = 0.f;
    for (int i = lane; i < D_; i += 32) {
        float x = xr[i];
#pragma unroll
        for (int c = 0; c < C_; c++) sc[c] += x * sWc[c * D_ + i];
    }
#pragma unroll
    for (int c = 0; c < C_; c++) {
#pragma unroll
        for (int off = 16; off > 0; off >>= 1)
            sc[c] += __shfl_xor_sync(0xffffffffu, sc[c], off);
    }
    if (lane == 0) {
        float best = sc[0] + sbc[0]; int bi = 0;
#pragma unroll
        for (int c = 1; c < C_; c++) {
            float v = sc[c] + sbc[c];
            if (v > best) { best = v; bi = c; }
        }
        g_assign[token] = bi;
    }
}

// ---------------------------------------------------------------------------
// Kernel 2: deterministic stream-compaction of token indices per (b, c).
// One block per (b,c); ballot + ordered block scan, ascending token order.
// ---------------------------------------------------------------------------
__global__ void compact_kernel()
{
    int bc = blockIdx.x;            // b*C + c
    int b = bc >> 3, c = bc & 7;
    __shared__ int warpTot[8];
    __shared__ int sBase;
    int tid = threadIdx.x;          // 256
    int lane = tid & 31, wid = tid >> 5;
    if (tid == 0) sBase = 0;
    __syncthreads();

    for (int t0 = 0; t0 < T_; t0 += 256) {
        int t = t0 + tid;
        bool flag = (g_assign[b * T_ + t] == c);
        unsigned bal = __ballot_sync(0xffffffffu, flag);
        int myPos = __popc(bal & ((1u << lane) - 1u));
        if (lane == 0) warpTot[wid] = __popc(bal);
        __syncthreads();
        int pre = 0;
        for (int wv = 0; wv < wid; wv++) pre += warpTot[wv];
        if (flag) g_idx[bc * T_ + sBase + pre + myPos] = t;
        __syncthreads();
        if (tid == 0) {
            int tot = 0;
            for (int wv = 0; wv < 8; wv++) tot += warpTot[wv];
            sBase += tot;
        }
        __syncthreads();
    }
    if (tid == 0) g_cnt[bc] = sBase;
}

// ---------------------------------------------------------------------------
// Kernel 3: fp32 SGEMM  Cmat[M,N] = A[M,K] @ W[N,K]^T + bias[N]
// 128x128x16 tiles, 8x8 per thread, 256 threads. Sizes are multiples of tiles.
// ---------------------------------------------------------------------------
__global__ __launch_bounds__(256) void sgemm_bias_kernel(
    const float* __restrict__ A, const float* __restrict__ W,
    const float* __restrict__ bias, float* __restrict__ Cmat,
    int M, int N, int K)
{
    __shared__ float As[16][128 + 4];
    __shared__ float Ws[16][128 + 4];
    int tid = threadIdx.x;
    int mBase = blockIdx.y * 128;
    int nBase = blockIdx.x * 128;
    int tx = tid & 15, ty = tid >> 4;

    float acc[8][8];
#pragma unroll
    for (int i = 0; i < 8; i++)
#pragma unroll
        for (int j = 0; j < 8; j++) acc[i][j] = 0.f;

    for (int k0 = 0; k0 < K; k0 += 16) {
        __syncthreads();
#pragma unroll
        for (int L = 0; L < 2; L++) {
            int li = tid + L * 256;
            int row = li >> 2;
            int kq = (li & 3) << 2;
            float4 a = *(const float4*)(A + (size_t)(mBase + row) * K + k0 + kq);
            As[kq + 0][row] = a.x; As[kq + 1][row] = a.y;
            As[kq + 2][row] = a.z; As[kq + 3][row] = a.w;
            float4 wv = *(const float4*)(W + (size_t)(nBase + row) * K + k0 + kq);
            Ws[kq + 0][row] = wv.x; Ws[kq + 1][row] = wv.y;
            Ws[kq + 2][row] = wv.z; Ws[kq + 3][row] = wv.w;
        }
        __syncthreads();
#pragma unroll
        for (int kk = 0; kk < 16; kk++) {
            float ar[8], br[8];
            float4 a0 = *(const float4*)&As[kk][ty * 8];
            float4 a1 = *(const float4*)&As[kk][ty * 8 + 4];
            ar[0] = a0.x; ar[1] = a0.y; ar[2] = a0.z; ar[3] = a0.w;
            ar[4] = a1.x; ar[5] = a1.y; ar[6] = a1.z; ar[7] = a1.w;
            float4 b0 = *(const float4*)&Ws[kk][tx * 8];
            float4 b1 = *(const float4*)&Ws[kk][tx * 8 + 4];
            br[0] = b0.x; br[1] = b0.y; br[2] = b0.z; br[3] = b0.w;
            br[4] = b1.x; br[5] = b1.y; br[6] = b1.z; br[7] = b1.w;
#pragma unroll
            for (int i = 0; i < 8; i++)
#pragma unroll
                for (int j = 0; j < 8; j++)
                    acc[i][j] += ar[i] * br[j];
        }
    }

    float bv[8];
#pragma unroll
    for (int j = 0; j < 8; j++) bv[j] = bias[nBase + tx * 8 + j];
#pragma unroll
    for (int i = 0; i < 8; i++) {
        float* cp = Cmat + (size_t)(mBase + ty * 8 + i) * N + nBase + tx * 8;
        float4 v0 = make_float4(acc[i][0] + bv[0], acc[i][1] + bv[1],
                                acc[i][2] + bv[2], acc[i][3] + bv[3]);
        float4 v1 = make_float4(acc[i][4] + bv[4], acc[i][5] + bv[5],
                                acc[i][6] + bv[6], acc[i][7] + bv[7]);
        *(float4*)cp = v0;
        *(float4*)(cp + 4) = v1;
    }
}

// ---------------------------------------------------------------------------
// Kernel 4: per-(b,c,h) compacted attention with zero-key softmax correction.
// Thread-per-query online softmax; K/V tiles of 32 keys staged in smem.
// Softmax init: m=0, l=(T-n) accounts for the (T-n) zero-score, zero-value
// keys from masked-out tokens in the reference.
// ---------------------------------------------------------------------------
__global__ __launch_bounds__(128) void attn_kernel()
{
    int h  = blockIdx.x & 7;
    int bc = blockIdx.x >> 3;   // b*C + c
    int b  = bc >> 3;
    int n  = g_cnt[bc];
    int q0 = blockIdx.y << 7;
    if (q0 >= n) return;

    int tid = threadIdx.x;
    int qi = q0 + tid;
    bool valid = qi < n;
    int tq = valid ? g_idx[bc * T_ + qi] : 0;

    __shared__ float sK[32][64];
    __shared__ float sV[32][64];

    float4 q4[16];
    {
        const float4* qp = (const float4*)(g_qkv + (size_t)(b * T_ + tq) * D3_ + h * HD_);
#pragma unroll
        for (int i = 0; i < 16; i++) q4[i] = qp[i];
    }
    float o[64];
#pragma unroll
    for (int d = 0; d < 64; d++) o[d] = 0.f;
    float m, l;
    if (n < T_) { m = 0.f; l = (float)(T_ - n); }
    else        { m = -3.0e38f; l = 0.f; }

    int r = tid >> 2;
    int part = (tid & 3) << 4;  // 0,16,32,48 floats

    for (int kt = 0; kt < n; kt += 32) {
        int nk = min(32, n - kt);
        __syncthreads();
        if (r < nk) {
            int tk = g_idx[bc * T_ + kt + r];
            const float* kp = g_qkv + (size_t)(b * T_ + tk) * D3_ + D_ + h * HD_ + part;
            const float* vp = kp + D_;
            float4* dK = (float4*)&sK[r][part];
            float4* dV = (float4*)&sV[r][part];
#pragma unroll
            for (int u = 0; u < 4; u++) {
                dK[u] = ((const float4*)kp)[u];
                dV[u] = ((const float4*)vp)[u];
            }
        }
        __syncthreads();
        if (valid) {
            for (int j = 0; j < nk; j++) {
                const float4* kr = (const float4*)sK[j];
                float s = 0.f;
#pragma unroll
                for (int i = 0; i < 16; i++) {
                    float4 kv = kr[i];
                    s += q4[i].x * kv.x + q4[i].y * kv.y +
                         q4[i].z * kv.z + q4[i].w * kv.w;
                }
                s *= 0.125f;  // 1/sqrt(64)
                if (s > m) {
                    float corr = __expf(m - s);
                    l *= corr;
#pragma unroll
                    for (int d = 0; d < 64; d++) o[d] *= corr;
                    m = s;
                }
                float p = __expf(s - m);
                l += p;
                const float4* vr = (const float4*)sV[j];
#pragma unroll
                for (int i = 0; i < 16; i++) {
                    float4 vv = vr[i];
                    o[4 * i + 0] += p * vv.x;
                    o[4 * i + 1] += p * vv.y;
                    o[4 * i + 2] += p * vv.z;
                    o[4 * i + 3] += p * vv.w;
                }
            }
        }
    }

    if (valid) {
        float inv = 1.f / l;
        float4* op = (float4*)(g_attn + (size_t)(b * T_ + tq) * D_ + h * HD_);
#pragma unroll
        for (int i = 0; i < 16; i++)
            op[i] = make_float4(o[4 * i + 0] * inv, o[4 * i + 1] * inv,
                                o[4 * i + 2] * inv, o[4 * i + 3] * inv);
    }
}

// ---------------------------------------------------------------------------
extern "C" void kernel_launch(void* const* d_in, const int* in_sizes, int n_in,
                              void* d_out, int out_size)
{
    (void)in_sizes; (void)n_in; (void)out_size;
    const float* X    = (const float*)d_in[0];
    const float* Wc   = (const float*)d_in[1];
    const float* bc   = (const float*)d_in[2];
    const float* Win  = (const float*)d_in[3];
    const float* bin  = (const float*)d_in[4];
    const float* Wout = (const float*)d_in[5];
    const float* bout = (const float*)d_in[6];
    float* out = (float*)d_out;

    float* qkv = nullptr;
    float* attn = nullptr;
    cudaGetSymbolAddress((void**)&qkv, g_qkv);
    cudaGetSymbolAddress((void**)&attn, g_attn);

    // 1) cluster argmax
    assign_kernel<<<BT_ / 4, 128>>>(X, Wc, bc);
    // 2) compact indices per (b,c)
    compact_kernel<<<B_ * C_, 256>>>();
    // 3) QKV projection: [4096,512] @ [512,1536]
    sgemm_bias_kernel<<<dim3(D3_ / 128, BT_ / 128), 256>>>(X, Win, bin, qkv,
                                                           BT_, D3_, D_);
    // 4) per-cluster attention
    attn_kernel<<<dim3(B_ * C_ * H_, T_ / 128), 128>>>();
    // 5) out projection: [4096,512] @ [512,512]
    sgemm_bias_kernel<<<dim3(D_ / 128, BT_ / 128), 256>>>(attn, Wout, bout, out,
                                                          BT_, D_, D_);
}

// round 8
// speedup vs baseline: 1.3854x; 1.3854x over previous
#include <cuda_runtime.h>
#include <cuda_bf16.h>
#include <cstdint>

// Problem constants
#define B_  4
#define T_  1024
#define D_  512
#define C_  8
#define H_  8
#define HD_ 64
#define BT_ (B_ * T_)      // 4096
#define D3_ (3 * D_)       // 1536

// Scratch (device globals: allocation-free, graph-capture safe)
__device__ float g_qkv[BT_ * D3_];            // [B*T, 3D] Q|K|V (fp32)
__device__ int   g_assign[BT_];               // cluster id per token
__device__ int   g_idx[B_ * C_ * T_];         // compacted token indices per (b,c)
__device__ int   g_cnt[B_ * C_];              // cluster sizes
__device__ __nv_bfloat16 g_xs[BT_ * 1024];    // X split   [r][0:512)=hi [512:1024)=lo
__device__ __nv_bfloat16 g_wins[D3_ * 1024];  // Win split
__device__ __nv_bfloat16 g_wouts[D_ * 1024];  // Wout split
__device__ __nv_bfloat16 g_attnsp[BT_ * 1024];// attention output, split hi|lo

// ---------------------------------------------------------------------------
// Kernel 1: cluster scores + argmax (exact fp32; '>' keeps first max).
// ---------------------------------------------------------------------------
__global__ void assign_kernel(const float* __restrict__ X,
                              const float* __restrict__ Wc,
                              const float* __restrict__ bc)
{
    __shared__ float sWc[C_ * D_];
    __shared__ float sbc[C_];
    int tid = threadIdx.x; // 128
    for (int i = tid; i < C_ * D_; i += 128) sWc[i] = Wc[i];
    if (tid < C_) sbc[tid] = bc[tid];
    __syncthreads();

    int lane = tid & 31, w = tid >> 5;
    int token = blockIdx.x * 4 + w;
    const float* xr = X + (size_t)token * D_;

    float sc[C_];
#pragma unroll
    for (int c = 0; c < C_; c++) sc[c] = 0.f;
    for (int i = lane; i < D_; i += 32) {
        float x = xr[i];
#pragma unroll
        for (int c = 0; c < C_; c++) sc[c] += x * sWc[c * D_ + i];
    }
#pragma unroll
    for (int c = 0; c < C_; c++) {
#pragma unroll
        for (int off = 16; off > 0; off >>= 1)
            sc[c] += __shfl_xor_sync(0xffffffffu, sc[c], off);
    }
    if (lane == 0) {
        float best = sc[0] + sbc[0]; int bi = 0;
#pragma unroll
        for (int c = 1; c < C_; c++) {
            float v = sc[c] + sbc[c];
            if (v > best) { best = v; bi = c; }
        }
        g_assign[token] = bi;
    }
}

// ---------------------------------------------------------------------------
// Kernel 2: deterministic stream-compaction per (b, c).
// ---------------------------------------------------------------------------
__global__ void compact_kernel()
{
    int bc = blockIdx.x;            // b*C + c
    int b = bc >> 3, c = bc & 7;
    __shared__ int warpTot[8];
    __shared__ int sBase;
    int tid = threadIdx.x;          // 256
    int lane = tid & 31, wid = tid >> 5;
    if (tid == 0) sBase = 0;
    __syncthreads();

    for (int t0 = 0; t0 < T_; t0 += 256) {
        int t = t0 + tid;
        bool flag = (g_assign[b * T_ + t] == c);
        unsigned bal = __ballot_sync(0xffffffffu, flag);
        int myPos = __popc(bal & ((1u << lane) - 1u));
        if (lane == 0) warpTot[wid] = __popc(bal);
        __syncthreads();
        int pre = 0;
        for (int wv = 0; wv < wid; wv++) pre += warpTot[wv];
        if (flag) g_idx[bc * T_ + sBase + pre + myPos] = t;
        __syncthreads();
        if (tid == 0) {
            int tot = 0;
            for (int wv = 0; wv < 8; wv++) tot += warpTot[wv];
            sBase += tot;
        }
        __syncthreads();
    }
    if (tid == 0) g_cnt[bc] = sBase;
}

// ---------------------------------------------------------------------------
// Kernel 3: fp32 -> bf16 hi/lo split.  src [rows][512] -> dst [rows][1024].
// ---------------------------------------------------------------------------
__global__ void split_kernel(const float* __restrict__ src,
                             __nv_bfloat16* __restrict__ dst)
{
    int r = blockIdx.x;
    int k = threadIdx.x << 1;
    float2 x = *(const float2*)(src + (size_t)r * 512 + k);
    __nv_bfloat16 h0 = __float2bfloat16(x.x);
    __nv_bfloat16 h1 = __float2bfloat16(x.y);
    __nv_bfloat16 l0 = __float2bfloat16(x.x - __bfloat162float(h0));
    __nv_bfloat16 l1 = __float2bfloat16(x.y - __bfloat162float(h1));
    *(__nv_bfloat162*)(dst + (size_t)r * 1024 + k)       = __halves2bfloat162(h0, h1);
    *(__nv_bfloat162*)(dst + (size_t)r * 1024 + 512 + k) = __halves2bfloat162(l0, l1);
}

// ---------------------------------------------------------------------------
// Kernel 4: bf16 split-3x tensor-core GEMM.
//   Cmat[M,N] = A[M,:512]*W[N,:512]^T  as Ah*Wh + Ah*Wl + Al*Wh  (fp32 accum)
// 128x128 block tile, 8 warps (2x4), warp tile 64x32, mma.m16n8k16 + ldmatrix.
// ---------------------------------------------------------------------------
__global__ __launch_bounds__(256) void mma_gemm_kernel(
    const __nv_bfloat16* __restrict__ A,
    const __nv_bfloat16* __restrict__ W,
    const float* __restrict__ bias,
    float* __restrict__ Cmat, int M, int N)
{
    __shared__ __nv_bfloat16 As[128 * 40];   // 128 rows x (32 + 8 pad)
    __shared__ __nv_bfloat16 Ws[128 * 40];
    int tid = threadIdx.x;
    int lane = tid & 31, wid = tid >> 5;
    int mBase = blockIdx.y * 128, nBase = blockIdx.x * 128;
    int wm = (wid & 1) * 64;
    int wn = (wid >> 1) * 32;

    float acc[4][4][4];
#pragma unroll
    for (int i = 0; i < 4; i++)
#pragma unroll
        for (int j = 0; j < 4; j++)
#pragma unroll
            for (int r = 0; r < 4; r++) acc[i][j][r] = 0.f;

    // ldmatrix per-lane row/col inside a 16x16 tile
    int lr = (lane & 7) + ((lane >> 3) & 1) * 8;   // 0..15
    int lc = (lane >> 4) * 8;                      // 0 or 8

    for (int pass = 0; pass < 3; pass++) {
        int aoff = (pass == 2) ? 512 : 0;
        int boff = (pass == 1) ? 512 : 0;
        for (int kt = 0; kt < 16; kt++) {
            int k0 = kt * 32;
            __syncthreads();
#pragma unroll
            for (int c = 0; c < 2; c++) {
                int id = tid + c * 256;
                int row = id >> 2, seg = (id & 3) * 8;
                *(uint4*)&As[row * 40 + seg] =
                    *(const uint4*)(A + (size_t)(mBase + row) * 1024 + aoff + k0 + seg);
                *(uint4*)&Ws[row * 40 + seg] =
                    *(const uint4*)(W + (size_t)(nBase + row) * 1024 + boff + k0 + seg);
            }
            __syncthreads();
#pragma unroll
            for (int kk = 0; kk < 2; kk++) {
                uint32_t af[4][4], bfr[2][4];
#pragma unroll
                for (int i = 0; i < 4; i++) {
                    uint32_t ad = (uint32_t)__cvta_generic_to_shared(
                        &As[(wm + i * 16 + lr) * 40 + kk * 16 + lc]);
                    asm volatile(
                        "ldmatrix.sync.aligned.m8n8.x4.shared.b16 {%0,%1,%2,%3}, [%4];"
                        : "=r"(af[i][0]), "=r"(af[i][1]), "=r"(af[i][2]), "=r"(af[i][3])
                        : "r"(ad));
                }
#pragma unroll
                for (int jj = 0; jj < 2; jj++) {
                    uint32_t bd = (uint32_t)__cvta_generic_to_shared(
                        &Ws[(wn + jj * 16 + lr) * 40 + kk * 16 + lc]);
                    asm volatile(
                        "ldmatrix.sync.aligned.m8n8.x4.shared.b16 {%0,%1,%2,%3}, [%4];"
                        : "=r"(bfr[jj][0]), "=r"(bfr[jj][1]), "=r"(bfr[jj][2]), "=r"(bfr[jj][3])
                        : "r"(bd));
                }
#pragma unroll
                for (int i = 0; i < 4; i++) {
#pragma unroll
                    for (int j = 0; j < 4; j++) {
                        uint32_t b0 = bfr[j >> 1][j & 1];
                        uint32_t b1 = bfr[j >> 1][2 + (j & 1)];
                        asm volatile(
                            "mma.sync.aligned.m16n8k16.row.col.f32.bf16.bf16.f32 "
                            "{%0,%1,%2,%3}, {%4,%5,%6,%7}, {%8,%9}, {%0,%1,%2,%3};"
                            : "+f"(acc[i][j][0]), "+f"(acc[i][j][1]),
                              "+f"(acc[i][j][2]), "+f"(acc[i][j][3])
                            : "r"(af[i][0]), "r"(af[i][1]), "r"(af[i][2]), "r"(af[i][3]),
                              "r"(b0), "r"(b1));
                    }
                }
            }
        }
    }

    // Epilogue: c0=(g,t*2) c1=(g,t*2+1) c2=(g+8,t*2) c3=(g+8,t*2+1)
    int g = lane >> 2, t = lane & 3;
#pragma unroll
    for (int i = 0; i < 4; i++) {
        int r0 = mBase + wm + i * 16 + g;
#pragma unroll
        for (int j = 0; j < 4; j++) {
            int col = nBase + wn + j * 8 + t * 2;
            float b0 = bias[col], b1 = bias[col + 1];
            *(float2*)(Cmat + (size_t)r0 * N + col) =
                make_float2(acc[i][j][0] + b0, acc[i][j][1] + b1);
            *(float2*)(Cmat + (size_t)(r0 + 8) * N + col) =
                make_float2(acc[i][j][2] + b0, acc[i][j][3] + b1);
        }
    }
}

// ---------------------------------------------------------------------------
// Kernel 5: per-(b,c,h) compacted attention. 2 threads per query (each owns
// 32 of 64 dims; score via full-mask shfl_xor pair-reduce — ALL threads run
// the loop uniformly; only the final store is predicated). Zero-key softmax
// correction l_init = T - n. Writes bf16 hi/lo split (out-proj A operand).
// ---------------------------------------------------------------------------
#define PADC(c) ((c) + (((c) >> 5) << 2))
__global__ __launch_bounds__(128) void attn_kernel()
{
    int h  = blockIdx.x & 7;
    int bc = blockIdx.x >> 3;   // b*C + c
    int b  = bc >> 3;
    int n  = g_cnt[bc];
    int q0 = blockIdx.y << 6;   // 64 queries per block
    if (q0 >= n) return;

    int tid = threadIdx.x;
    int half = tid & 1;
    int qi = q0 + (tid >> 1);
    bool valid = qi < n;
    int tq = g_idx[bc * T_ + (valid ? qi : 0)];

    __shared__ float sK[32][68];
    __shared__ float sV[32][68];

    float4 q4[8];
    {
        const float4* qp = (const float4*)(g_qkv + (size_t)(b * T_ + tq) * D3_
                                           + h * HD_ + half * 32);
#pragma unroll
        for (int i = 0; i < 8; i++) q4[i] = qp[i];
    }
    float o[32];
#pragma unroll
    for (int d = 0; d < 32; d++) o[d] = 0.f;
    float m, l;
    if (n < T_) { m = 0.f; l = (float)(T_ - n); }
    else        { m = -3.0e38f; l = 0.f; }

    int r = tid >> 2;                 // key row 0..31
    int part = (tid & 3) << 4;        // 0,16,32,48 floats
    int rbase = half * 36;            // padded read base

    for (int kt = 0; kt < n; kt += 32) {
        int nk = min(32, n - kt);
        __syncthreads();
        if (r < nk) {
            int tk = g_idx[bc * T_ + kt + r];
            const float4* kp = (const float4*)(g_qkv + (size_t)(b * T_ + tk) * D3_
                                               + D_ + h * HD_ + part);
            const float4* vp = kp + (D_ / 4);
            float4* dK = (float4*)&sK[r][PADC(part)];
            float4* dV = (float4*)&sV[r][PADC(part)];
#pragma unroll
            for (int u = 0; u < 4; u++) {
                dK[u] = kp[u];
                dV[u] = vp[u];
            }
        }
        __syncthreads();
        // All threads execute uniformly (invalid pairs compute on token
        // g_idx[0]'s real data — bounded garbage, discarded at store).
        for (int j = 0; j < nk; j++) {
            const float4* kr = (const float4*)&sK[j][rbase];
            float s = 0.f;
#pragma unroll
            for (int i = 0; i < 8; i++) {
                float4 kv = kr[i];
                s += q4[i].x * kv.x + q4[i].y * kv.y +
                     q4[i].z * kv.z + q4[i].w * kv.w;
            }
            s += __shfl_xor_sync(0xffffffffu, s, 1);
            s *= 0.125f;  // 1/sqrt(64)
            if (s > m) {
                float corr = __expf(m - s);
                l *= corr;
#pragma unroll
                for (int d = 0; d < 32; d++) o[d] *= corr;
                m = s;
            }
            float p = __expf(s - m);
            l += p;
            const float4* vr = (const float4*)&sV[j][rbase];
#pragma unroll
            for (int i = 0; i < 8; i++) {
                float4 vv = vr[i];
                o[4 * i + 0] += p * vv.x;
                o[4 * i + 1] += p * vv.y;
                o[4 * i + 2] += p * vv.z;
                o[4 * i + 3] += p * vv.w;
            }
        }
    }

    if (valid) {
        float inv = 1.f / l;
        size_t row = (size_t)(b * T_ + tq);
        __nv_bfloat16* hp = g_attnsp + row * 1024 + h * HD_ + half * 32;
        __nv_bfloat16* lp = hp + 512;
#pragma unroll
        for (int d = 0; d < 32; d += 2) {
            float v0 = o[d] * inv, v1 = o[d + 1] * inv;
            __nv_bfloat16 h0 = __float2bfloat16(v0);
            __nv_bfloat16 h1 = __float2bfloat16(v1);
            __nv_bfloat16 l0 = __float2bfloat16(v0 - __bfloat162float(h0));
            __nv_bfloat16 l1 = __float2bfloat16(v1 - __bfloat162float(h1));
            *(__nv_bfloat162*)(hp + d) = __halves2bfloat162(h0, h1);
            *(__nv_bfloat162*)(lp + d) = __halves2bfloat162(l0, l1);
        }
    }
}

// ---------------------------------------------------------------------------
extern "C" void kernel_launch(void* const* d_in, const int* in_sizes, int n_in,
                              void* d_out, int out_size)
{
    (void)in_sizes; (void)n_in; (void)out_size;
    const float* X    = (const float*)d_in[0];
    const float* Wc   = (const float*)d_in[1];
    const float* bc   = (const float*)d_in[2];
    const float* Win  = (const float*)d_in[3];
    const float* bin  = (const float*)d_in[4];
    const float* Wout = (const float*)d_in[5];
    const float* bout = (const float*)d_in[6];
    float* out = (float*)d_out;

    float* qkv = nullptr;
    __nv_bfloat16 *xs = nullptr, *wins = nullptr, *wouts = nullptr, *attnsp = nullptr;
    cudaGetSymbolAddress((void**)&qkv,    g_qkv);
    cudaGetSymbolAddress((void**)&xs,     g_xs);
    cudaGetSymbolAddress((void**)&wins,   g_wins);
    cudaGetSymbolAddress((void**)&wouts,  g_wouts);
    cudaGetSymbolAddress((void**)&attnsp, g_attnsp);

    // 1) cluster argmax (exact fp32)
    assign_kernel<<<BT_ / 4, 128>>>(X, Wc, bc);
    // 2) compact indices per (b,c)
    compact_kernel<<<B_ * C_, 256>>>();
    // 3) bf16 hi/lo splits
    split_kernel<<<BT_, 256>>>(X, xs);
    split_kernel<<<D3_, 256>>>(Win, wins);
    split_kernel<<<D_, 256>>>(Wout, wouts);
    // 4) QKV projection: [4096,512] @ [512,1536]^T  (split-3x tensor cores)
    mma_gemm_kernel<<<dim3(D3_ / 128, BT_ / 128), 256>>>(xs, wins, bin, qkv,
                                                         BT_, D3_);
    // 5) per-cluster attention (fp32 softmax path, writes split bf16)
    attn_kernel<<<dim3(B_ * C_ * H_, T_ / 64), 128>>>();
    // 6) out projection: [4096,512] @ [512,512]^T
    mma_gemm_kernel<<<dim3(D_ / 128, BT_ / 128), 256>>>(attnsp, wouts, bout, out,
                                                        BT_, D_);
}